// round 16
// baseline (speedup 1.0000x reference)
#include <cuda_runtime.h>
#include <cstdint>

// LoRA forward: out = (x @ B) @ A * 2
//   x: [8192, 4096] fp32, B: [4096, 16], A: [16, 4096], out: [8192, 4096]
//  lora_xb : NEW: 128 rows/block, 4 rows/lane (halves B-broadcast LDS, the
//            dominant L1 term), 2-stage cp.async, occ 2, i-split x8.
//  lora_out: FROZEN R4 config (~30us), prologue sums 8 partials.

#define ROWS_TOTAL 8192
#define IN_DIM     4096
#define OUT_DIM    4096
#define R_DIM      16

#define XB_SPLIT   8
#define XB_ISPAN   (IN_DIM / XB_SPLIT)     // 512 i per block
#define XB_AT      32                       // i per tile
#define XB_NT      (XB_ISPAN / XB_AT)       // 16 tiles
#define XB_ROWS    128                      // rows per block (4 per lane)

typedef unsigned long long u64;

// partial xb: [split][row][8] u64, each u64 = (xb_{2j}, xb_{2j+1}), scaled by 2
__device__ u64 g_xbp[XB_SPLIT][ROWS_TOTAL][R_DIM / 2];

// ---------- packed f32x2 helpers ----------
__device__ __forceinline__ u64 pack2(float lo, float hi) {
    u64 r; asm("mov.b64 %0, {%1, %2};" : "=l"(r) : "f"(lo), "f"(hi)); return r;
}
__device__ __forceinline__ void unpack2(u64 v, float& lo, float& hi) {
    asm("mov.b64 {%0, %1}, %2;" : "=f"(lo), "=f"(hi) : "l"(v));
}
__device__ __forceinline__ void ffma2(u64& d, u64 a, u64 b) {
    asm("fma.rn.f32x2 %0, %1, %2, %0;" : "+l"(d) : "l"(a), "l"(b));
}
__device__ __forceinline__ void addf2(u64& d, u64 a, u64 b) {
    asm("add.rn.f32x2 %0, %1, %2;" : "=l"(d) : "l"(a), "l"(b));
}
__device__ __forceinline__ void mulf2(u64& d, u64 a, u64 b) {
    asm("mul.rn.f32x2 %0, %1, %2;" : "=l"(d) : "l"(a), "l"(b));
}

// ---------- cp.async helpers ----------
__device__ __forceinline__ uint32_t s2u(const void* p) {
    return (uint32_t)__cvta_generic_to_shared(p);
}
__device__ __forceinline__ void cp16(uint32_t dst, const void* src) {
    asm volatile("cp.async.cg.shared.global [%0], [%1], 16;"
                 :: "r"(dst), "l"(src) : "memory");
}
#define CP_COMMIT()  asm volatile("cp.async.commit_group;" ::: "memory")
#define CP_WAIT(N)   asm volatile("cp.async.wait_group %0;" :: "n"(N) : "memory")

// ---------- kernel A: partial xb (4 rows/lane) ----------
// 256 threads = 8 warps. Warp w covers i-float4 slot w (4 i's) of each 32-i
// tile. Lane covers rows {lane, lane+32, lane+64, lane+96}. B broadcast
// LDS.128 serves 4 rows (8 ffma2 x 4 = 32 per 4 loads). x XOR-swizzled.
// 2-stage cp.async double buffer. occ 2 (128-reg cap; live set ~115).
__global__ void __launch_bounds__(256, 2) lora_xb(const float* __restrict__ x,
                                                  const float* __restrict__ B) {
    __shared__ float xs[2][XB_ROWS][XB_AT];   // 2 x 16 KB
    __shared__ float bs[2][XB_AT][R_DIM];     // 2 x  2 KB

    const int tid   = threadIdx.x;
    const int wid   = tid >> 5;
    const int lane  = tid & 31;
    const int row0  = (blockIdx.x >> 3) * XB_ROWS;
    const int split = blockIdx.x & 7;
    const int i0    = split * XB_ISPAN;

    const float4* xg = reinterpret_cast<const float4*>(x);
    const float4* Bg = reinterpret_cast<const float4*>(B);   // B row i = 4 float4

    auto stage = [&](int it, int buf) {
        float4* xs4 = reinterpret_cast<float4*>(&xs[buf][0][0]);   // [128][8]
        float4* bs4 = reinterpret_cast<float4*>(&bs[buf][0][0]);   // [128]
        // x: 128 rows x 8 float4 = 1024 -> 4 per thread, XOR-swizzled dst
#pragma unroll
        for (int k = 0; k < 4; k++) {
            int f  = tid + k * 256;
            int rw = f >> 3;          // 0..127
            int c4 = f & 7;           // 0..7
            cp16(s2u(&xs4[rw * 8 + (c4 ^ (rw & 7))]),
                 &xg[(size_t)(row0 + rw) * (IN_DIM / 4) + (i0 >> 2) + it * (XB_AT / 4) + c4]);
        }
        // B tile: 32 rows x 4 float4 = 128 contiguous -> threads 0..127
        if (tid < 128)
            cp16(s2u(&bs4[tid]), &Bg[(size_t)(i0 + it * XB_AT) * 4 + tid]);
        CP_COMMIT();
    };

    stage(0, 0);

    u64 acc[4][8];
#pragma unroll
    for (int rw = 0; rw < 4; rw++)
#pragma unroll
        for (int j = 0; j < 8; j++) acc[rw][j] = 0ull;

    for (int it = 0; it < XB_NT; it++) {
        const int buf = it & 1;
        if (it + 1 < XB_NT) { stage(it + 1, buf ^ 1); CP_WAIT(1); }
        else                { CP_WAIT(0); }
        __syncthreads();   // tile `it` visible everywhere

        const float4*     xs4 = reinterpret_cast<const float4*>(&xs[buf][0][0]);
        const ulonglong2* bs2 = reinterpret_cast<const ulonglong2*>(&bs[buf][0][0]);

        // x for this warp's float4 slot (wid), 4 rows (swizzle row-uniform:
        // (lane + 32*rw) & 7 == lane & 7)
        float4 xq[4];
#pragma unroll
        for (int rw = 0; rw < 4; rw++)
            xq[rw] = xs4[(lane + 32 * rw) * 8 + (wid ^ (lane & 7))];
        float xe[4][4] = {
            {xq[0].x, xq[0].y, xq[0].z, xq[0].w},
            {xq[1].x, xq[1].y, xq[1].z, xq[1].w},
            {xq[2].x, xq[2].y, xq[2].z, xq[2].w},
            {xq[3].x, xq[3].y, xq[3].z, xq[3].w}};

#pragma unroll
        for (int e = 0; e < 4; e++) {
            const int il = wid * 4 + e;            // i within tile
            ulonglong2 b01 = bs2[il * 4 + 0];      // broadcast: r0..3
            ulonglong2 b23 = bs2[il * 4 + 1];      // r4..7
            ulonglong2 b45 = bs2[il * 4 + 2];      // r8..11
            ulonglong2 b67 = bs2[il * 4 + 3];      // r12..15
#pragma unroll
            for (int rw = 0; rw < 4; rw++) {
                u64 xx = pack2(xe[rw][e], xe[rw][e]);
                ffma2(acc[rw][0], xx, b01.x);
                ffma2(acc[rw][1], xx, b01.y);
                ffma2(acc[rw][2], xx, b23.x);
                ffma2(acc[rw][3], xx, b23.y);
                ffma2(acc[rw][4], xx, b45.x);
                ffma2(acc[rw][5], xx, b45.y);
                ffma2(acc[rw][6], xx, b67.x);
                ffma2(acc[rw][7], xx, b67.y);
            }
        }
        __syncthreads();   // compute done before buffer `buf` is restaged
    }

    // cross-warp reduction, 2 passes through xs (16 KB x 2 stages = 4096 u64)
    u64* red = reinterpret_cast<u64*>(&xs[0][0][0]);
    u64 two = pack2(2.0f, 2.0f);
#pragma unroll
    for (int p = 0; p < 2; p++) {
        // store rows rw = 2p, 2p+1 : 256 thr x 16 u64 = 4096 u64
#pragma unroll
        for (int rsel = 0; rsel < 2; rsel++)
#pragma unroll
            for (int j = 0; j < 8; j++)
                red[(wid * 32 + lane) * 16 + rsel * 8 + j] = acc[2 * p + rsel][j];
        __syncthreads();

        // reduce 512 items (lrow 0..31, rsel 0..1, slot 0..7) over 8 warps
#pragma unroll
        for (int k = 0; k < 2; k++) {
            const int item = tid + k * 256;        // 0..511
            const int lrow = item >> 4;            // 0..31
            const int rsel = (item >> 3) & 1;
            const int slot = item & 7;
            u64 s = red[(0 * 32 + lrow) * 16 + rsel * 8 + slot];
#pragma unroll
            for (int w = 1; w < 8; w++)
                addf2(s, s, red[(w * 32 + lrow) * 16 + rsel * 8 + slot]);
            mulf2(s, s, two);                      // LoRA scale folded here
            const int row = lrow + 32 * (2 * p + rsel);
            g_xbp[split][row0 + row][slot] = s;
        }
        __syncthreads();   // scratch free before next pass
    }
}

// ---------- kernel B: out = xb @ A (FROZEN R4 design) ----------
// 128 threads; block covers 64 rows x 512 cols. A slice (16 r x 1 ulonglong2)
// in regs; xb (sum of 8 splits) broadcast from smem. Grid 1024.
#define O_ROWS 64

__global__ void __launch_bounds__(128, 4) lora_out(const float* __restrict__ A,
                                                   float* __restrict__ out) {
    __shared__ u64 xbs[O_ROWS * R_DIM];   // 8 KB, entries packed (v,v)

    const int tid    = threadIdx.x;
    const int rowblk = blockIdx.x >> 3;
    const int colblk = blockIdx.x & 7;
    const int row0   = rowblk * O_ROWS;

    // fill xbs: 64 rows * 8 u64-slots = 512 -> 4 per thread; sum the 8 splits
    {
        const u64* gp = &g_xbp[0][row0][0];
        const size_t sstr = (size_t)ROWS_TOTAL * (R_DIM / 2);
#pragma unroll
        for (int k = 0; k < 4; k++) {
            int j = tid + k * 128;            // j -> (row = j>>3, slot = j&7)
            u64 s0, s1, s2, s3;
            addf2(s0, gp[0 * sstr + j], gp[1 * sstr + j]);
            addf2(s1, gp[2 * sstr + j], gp[3 * sstr + j]);
            addf2(s2, gp[4 * sstr + j], gp[5 * sstr + j]);
            addf2(s3, gp[6 * sstr + j], gp[7 * sstr + j]);
            addf2(s0, s0, s1);
            addf2(s2, s2, s3);
            addf2(s0, s0, s2);
            float f0, f1;
            unpack2(s0, f0, f1);
            int rw = j >> 3, slot = j & 7;
            xbs[rw * R_DIM + slot * 2 + 0] = pack2(f0, f0);
            xbs[rw * R_DIM + slot * 2 + 1] = pack2(f1, f1);
        }
    }
    __syncthreads();

    // A slice into registers: 16 r x 1 ulonglong2 (4 cols), coalesced
    const ulonglong2* Av = reinterpret_cast<const ulonglong2*>(A);  // [16][1024]
    const int cu = colblk * 128 + tid;    // ulonglong2 index within a row
    ulonglong2 Ar[R_DIM];
#pragma unroll
    for (int rr = 0; rr < R_DIM; rr++)
        Ar[rr] = Av[(size_t)rr * (OUT_DIM / 4) + cu];

    ulonglong2* outv = reinterpret_cast<ulonglong2*>(out);
    const ulonglong2* xu = reinterpret_cast<const ulonglong2*>(xbs);

#pragma unroll 2
    for (int rw = 0; rw < O_ROWS; rw++) {
        u64 a0e = 0ull, a0o = 0ull, a1e = 0ull, a1o = 0ull;
#pragma unroll
        for (int q = 0; q < 8; q++) {
            ulonglong2 xq = xu[rw * 8 + q];   // bcast (xb_2q,xb_2q),(xb_2q+1,..)
            ffma2(a0e, xq.x, Ar[2 * q].x);
            ffma2(a1e, xq.x, Ar[2 * q].y);
            ffma2(a0o, xq.y, Ar[2 * q + 1].x);
            ffma2(a1o, xq.y, Ar[2 * q + 1].y);
        }
        u64 o0, o1;
        addf2(o0, a0e, a0o);
        addf2(o1, a1e, a1o);
        ulonglong2 v; v.x = o0; v.y = o1;
        outv[(size_t)(row0 + rw) * (OUT_DIM / 4) + cu] = v;   // STG.128 coalesced
    }
}

// ---------- launch ----------
extern "C" void kernel_launch(void* const* d_in, const int* in_sizes, int n_in,
                              void* d_out, int out_size) {
    const float* x  = (const float*)d_in[0];   // [4, 2048, 4096]
    const float* lA = (const float*)d_in[1];   // [16, 4096]
    const float* lB = (const float*)d_in[2];   // [4096, 16]
    float* out = (float*)d_out;

    lora_xb<<<(ROWS_TOTAL / XB_ROWS) * XB_SPLIT, 256>>>(x, lB);          // 512
    lora_out<<<(ROWS_TOTAL / O_ROWS) * (OUT_DIM / 512), 128>>>(lA, out); // 1024
}